// round 15
// baseline (speedup 1.0000x reference)
#include <cuda_runtime.h>

// PrevEmbedding, two-phase:
//   Phase 1 (tiny): pt[t,:] = LN(pos_emb[t]+type_emb[ty])*emb_g+emb_b   (T=128 rows)
//   Phase 2:        out[row,:] = LN(gathered_row)*g+b + pt[t,:]
// - LN only the 2048 gathered rows, never the 32000x768 table
// - phase 2: 2 warps/row, 3 float4/lane, named pair barrier, st.cs stores
// - gamma/beta staged in smem per CTA (epilogue via LDS, off the L1tex queue)
// - pt stream is L2-hot (384KB); pe/te/eg/eb loads + half the reduction removed

#define HD     768
#define V4c    (HD / 4)      // 192 float4 per row
#define LN_EPS 1e-5f
#define MAX_T  256

__device__ float g_pt[MAX_T * HD];

__device__ __forceinline__ void stcs4(float4* p, float4 v) {
    asm volatile("st.global.cs.v4.f32 [%0], {%1,%2,%3,%4};"
                 :: "l"(p), "f"(v.x), "f"(v.y), "f"(v.z), "f"(v.w) : "memory");
}

// ---------------- Phase 1: pos+type LN, warp-per-row ----------------
__global__ __launch_bounds__(128)
void pt_kernel(const float* __restrict__ pos_emb,   // [T, H]
               const float* __restrict__ type_emb,  // [2, H]
               const float* __restrict__ emb_g,
               const float* __restrict__ emb_b,
               int V, int T)
{
    const int wid  = threadIdx.x >> 5;
    const int lane = threadIdx.x & 31;
    const int t    = blockIdx.x * 4 + wid;
    if (t >= T) return;

    const int type_id = (t >= V) ? 1 : 0;          // faithful (0 here)
    const float4* pe4 = (const float4*)(pos_emb + t * HD);
    const float4* te4 = (const float4*)(type_emb + type_id * HD);

    float4 p[6];
    #pragma unroll
    for (int j = 0; j < 6; j++) {
        float4 a = pe4[lane + 32 * j];
        float4 c = te4[lane + 32 * j];
        p[j] = make_float4(a.x + c.x, a.y + c.y, a.z + c.z, a.w + c.w);
    }

    float sp = 0.f, spp = 0.f;
    #pragma unroll
    for (int j = 0; j < 6; j++) {
        sp  += p[j].x + p[j].y + p[j].z + p[j].w;
        spp += p[j].x*p[j].x + p[j].y*p[j].y + p[j].z*p[j].z + p[j].w*p[j].w;
    }
    #pragma unroll
    for (int off = 16; off > 0; off >>= 1) {
        sp  += __shfl_xor_sync(0xFFFFFFFFu, sp,  off);
        spp += __shfl_xor_sync(0xFFFFFFFFu, spp, off);
    }

    const float inv_h = 1.0f / (float)HD;
    const float mu = sp * inv_h;
    const float r  = rsqrtf(fmaxf(spp * inv_h - mu * mu, 0.f) + LN_EPS);

    const float4* eg4 = (const float4*)emb_g;
    const float4* eb4 = (const float4*)emb_b;
    float4* o = (float4*)(g_pt + t * HD);
    #pragma unroll
    for (int j = 0; j < 6; j++) {
        const int h = lane + 32 * j;
        const float4 g = eg4[h];
        const float4 b = eb4[h];
        float4 v;
        v.x = (p[j].x - mu) * r * g.x + b.x;
        v.y = (p[j].y - mu) * r * g.y + b.y;
        v.z = (p[j].z - mu) * r * g.z + b.z;
        v.w = (p[j].w - mu) * r * g.w + b.w;
        o[h] = v;
    }
}

// ---------------- Phase 2: gather + LN + add pt ----------------
#define TPB    256           // 8 warps = 4 row-pairs per CTA
#define RPC    4
#define NPAR   (4 * V4c)     // cv_g|cv_b|ocr_g|ocr_b staged

__global__ __launch_bounds__(TPB)
void prev_embedding_kernel(
    const float* __restrict__ cv,        // [V, H]
    const float* __restrict__ ocr,       // [B, N, H]
    const int*   __restrict__ raw,       // [B*T] int32 view (maybe int64 data)
    const float* __restrict__ cv_g,
    const float* __restrict__ cv_b,
    const float* __restrict__ ocr_g,
    const float* __restrict__ ocr_b,
    float* __restrict__ out,             // [B*T, H]
    int V, int N, int T, int BT)
{
    __shared__ float4 s_par[NPAR];       // [cv_g | cv_b | ocr_g | ocr_b]
    __shared__ float4 s_red[RPC][2];     // per-pair partial stats {sx,sxx,-,-}

    const int tid  = threadIdx.x;
    const int wid  = tid >> 5;
    const int lane = tid & 31;
    const int pair = wid >> 1;
    const int wip  = wid & 1;
    const int h0   = wip * 32 + lane;    // 0..63
    const int row  = blockIdx.x * RPC + pair;
    const bool active = (row < BT);

    // Stage gamma/beta params (independent of everything; issues first).
    {
        const float* srcs[4] = { cv_g, cv_b, ocr_g, ocr_b };
        #pragma unroll
        for (int i = tid; i < NPAR; i += TPB) {
            const int a = i / V4c;
            const int e = i - a * V4c;
            s_par[i] = ((const float4*)srcs[a])[e];
        }
    }

    float4 x[3], pt[3];
    float mu_x = 0.f, rx = 0.f;
    bool use_ocr = false;

    if (active) {
        // id fetch: both dtype candidates + probes in parallel.
        const int pr   = raw[1] | raw[3] | raw[5] | raw[7];
        const int id32 = raw[row];
        const int id64 = raw[2 * row];
        const int id   = (pr == 0) ? id64 : id32;

        const int b = row / T;
        const int t = row - b * T;

        // pt loads (id-independent, L2-hot): in flight during id selection.
        const float4* pt4 = (const float4*)(g_pt + t * HD);
        #pragma unroll
        for (int j = 0; j < 3; j++) pt[j] = pt4[h0 + 64 * j];

        const float* src;
        use_ocr = (id >= V);
        if (use_ocr) {
            int oi = id - V;
            if (oi > N - 1) oi = N - 1;
            src = ocr + ((long long)b * N + oi) * HD;
        } else {
            int ci = id < 0 ? 0 : (id > V - 1 ? V - 1 : id);
            src = cv + (long long)ci * HD;
        }
        const float4* s4 = (const float4*)src;
        #pragma unroll
        for (int j = 0; j < 3; j++) x[j] = s4[h0 + 64 * j];

        float sx = 0.f, sxx = 0.f;
        #pragma unroll
        for (int j = 0; j < 3; j++) {
            sx  += x[j].x + x[j].y + x[j].z + x[j].w;
            sxx += x[j].x*x[j].x + x[j].y*x[j].y + x[j].z*x[j].z + x[j].w*x[j].w;
        }
        #pragma unroll
        for (int off = 16; off > 0; off >>= 1) {
            sx  += __shfl_xor_sync(0xFFFFFFFFu, sx,  off);
            sxx += __shfl_xor_sync(0xFFFFFFFFu, sxx, off);
        }
        if (lane == 0) s_red[pair][wip] = make_float4(sx, sxx, 0.f, 0.f);
    }

    __syncthreads();   // staged params + pair stats visible

    if (active) {
        const float4 r0 = s_red[pair][0];
        const float4 r1 = s_red[pair][1];
        const float inv_h = 1.0f / (float)HD;
        mu_x = (r0.x + r1.x) * inv_h;
        rx   = rsqrtf(fmaxf((r0.y + r1.y) * inv_h - mu_x * mu_x, 0.f) + LN_EPS);

        const float4* gm = s_par + (use_ocr ? 2 * V4c : 0);
        const float4* bm = gm + V4c;
        float4* o = (float4*)(out + (long long)row * HD);

        #pragma unroll
        for (int j = 0; j < 3; j++) {
            const int h = h0 + 64 * j;
            const float4 g  = gm[h];
            const float4 bb = bm[h];
            float4 r;
            r.x = (x[j].x - mu_x) * rx * g.x + bb.x + pt[j].x;
            r.y = (x[j].y - mu_x) * rx * g.y + bb.y + pt[j].y;
            r.z = (x[j].z - mu_x) * rx * g.z + bb.z + pt[j].z;
            r.w = (x[j].w - mu_x) * rx * g.w + bb.w + pt[j].w;
            stcs4(o + h, r);
        }
    }
}

extern "C" void kernel_launch(void* const* d_in, const int* in_sizes, int n_in,
                              void* d_out, int out_size) {
    const float* cv       = (const float*)d_in[0];   // [V, H]
    const float* ocr      = (const float*)d_in[1];   // [B, N, H]
    const int*   ids_raw  = (const int*)d_in[2];     // [B, T] int32 or int64
    const float* cv_g     = (const float*)d_in[3];
    const float* cv_b     = (const float*)d_in[4];
    const float* ocr_g    = (const float*)d_in[5];
    const float* ocr_b    = (const float*)d_in[6];
    const float* pos_emb  = (const float*)d_in[7];   // [T, H]
    const float* type_emb = (const float*)d_in[8];   // [2, H]
    const float* emb_g    = (const float*)d_in[9];
    const float* emb_b    = (const float*)d_in[10];
    float* out = (float*)d_out;

    const int Hs = in_sizes[3];             // 768
    const int V  = in_sizes[0] / Hs;        // 32000
    const int T  = in_sizes[7] / Hs;        // 128
    const int BT = in_sizes[2];             // 2048
    const int B  = BT / T;                  // 16
    const int N  = in_sizes[1] / (B * Hs);  // 50

    pt_kernel<<<(T + 3) / 4, 128>>>(pos_emb, type_emb, emb_g, emb_b, V, T);

    const int grid = (BT + RPC - 1) / RPC;  // 512
    prev_embedding_kernel<<<grid, TPB>>>(cv, ocr, ids_raw,
                                         cv_g, cv_b, ocr_g, ocr_b,
                                         out, V, N, T, BT);
}

// round 16
// speedup vs baseline: 1.2555x; 1.2555x over previous
#include <cuda_runtime.h>

// PrevEmbedding, two-phase, R12-skeleton:
//   Phase 1 (tiny, ~free): pt[t,:] = LN(pos_emb[t]+type_emb[ty])*emb_g+emb_b  (T=128)
//   Phase 2: out[row,:] = LN(gathered_row)*g+b + pt[t,:]
// Phase 2 keeps the measured-best R12 structure exactly:
//   - 2 warps/row, 3 float4/lane, named pair barrier (no CTA-wide sync)
//   - params straight from L1 (NO smem staging), st.cs streaming stores
//   - id dtype candidates loaded in parallel with probes
// Delta vs R12: pe/te loads+2nd reduction replaced by 3 L2-hot pt loads,
// epilogue param loads halved.

#define HD     768
#define LN_EPS 1e-5f
#define MAX_T  256

__device__ float g_pt[MAX_T * HD];

__device__ __forceinline__ void stcs4(float4* p, float4 v) {
    asm volatile("st.global.cs.v4.f32 [%0], {%1,%2,%3,%4};"
                 :: "l"(p), "f"(v.x), "f"(v.y), "f"(v.z), "f"(v.w) : "memory");
}

// ---------------- Phase 1: pos+type LN, warp-per-row ----------------
__global__ __launch_bounds__(128)
void pt_kernel(const float* __restrict__ pos_emb,   // [T, H]
               const float* __restrict__ type_emb,  // [2, H]
               const float* __restrict__ emb_g,
               const float* __restrict__ emb_b,
               int V, int T)
{
    const int wid  = threadIdx.x >> 5;
    const int lane = threadIdx.x & 31;
    const int t    = blockIdx.x * 4 + wid;
    if (t >= T) return;

    const int type_id = (t >= V) ? 1 : 0;          // faithful (0 here)
    const float4* pe4 = (const float4*)(pos_emb + t * HD);
    const float4* te4 = (const float4*)(type_emb + type_id * HD);

    float4 p[6];
    #pragma unroll
    for (int j = 0; j < 6; j++) {
        float4 a = pe4[lane + 32 * j];
        float4 c = te4[lane + 32 * j];
        p[j] = make_float4(a.x + c.x, a.y + c.y, a.z + c.z, a.w + c.w);
    }

    float sp = 0.f, spp = 0.f;
    #pragma unroll
    for (int j = 0; j < 6; j++) {
        sp  += p[j].x + p[j].y + p[j].z + p[j].w;
        spp += p[j].x*p[j].x + p[j].y*p[j].y + p[j].z*p[j].z + p[j].w*p[j].w;
    }
    #pragma unroll
    for (int off = 16; off > 0; off >>= 1) {
        sp  += __shfl_xor_sync(0xFFFFFFFFu, sp,  off);
        spp += __shfl_xor_sync(0xFFFFFFFFu, spp, off);
    }

    const float inv_h = 1.0f / (float)HD;
    const float mu = sp * inv_h;
    const float r  = rsqrtf(fmaxf(spp * inv_h - mu * mu, 0.f) + LN_EPS);

    const float4* eg4 = (const float4*)emb_g;
    const float4* eb4 = (const float4*)emb_b;
    float4* o = (float4*)(g_pt + t * HD);
    #pragma unroll
    for (int j = 0; j < 6; j++) {
        const int h = lane + 32 * j;
        const float4 g = eg4[h];
        const float4 b = eb4[h];
        float4 v;
        v.x = (p[j].x - mu) * r * g.x + b.x;
        v.y = (p[j].y - mu) * r * g.y + b.y;
        v.z = (p[j].z - mu) * r * g.z + b.z;
        v.w = (p[j].w - mu) * r * g.w + b.w;
        o[h] = v;
    }
}

// ---------------- Phase 2: gather + LN + add pt (R12 skeleton) ----------------
#define TPB    256           // 8 warps = 4 row-pairs per CTA
#define RPC    4

__global__ __launch_bounds__(TPB)
void prev_embedding_kernel(
    const float* __restrict__ cv,        // [V, H]
    const float* __restrict__ ocr,       // [B, N, H]
    const int*   __restrict__ raw,       // [B*T] int32 view (maybe int64 data)
    const float* __restrict__ cv_g,
    const float* __restrict__ cv_b,
    const float* __restrict__ ocr_g,
    const float* __restrict__ ocr_b,
    float* __restrict__ out,             // [B*T, H]
    int V, int N, int T, int BT)
{
    __shared__ float2 s_red[RPC][2];     // [pair][warpInPair] = {sx,sxx}

    const int tid  = threadIdx.x;
    const int wid  = tid >> 5;
    const int lane = tid & 31;
    const int pair = wid >> 1;
    const int wip  = wid & 1;
    const int h0   = wip * 32 + lane;    // 0..63
    const int row  = blockIdx.x * RPC + pair;
    if (row >= BT) return;

    // id fetch: both dtype candidates + probes in parallel.
    const int pr   = raw[1] | raw[3] | raw[5] | raw[7];  // uniform, L1 broadcast
    const int id32 = raw[row];
    const int id64 = raw[2 * row];
    const int id   = (pr == 0) ? id64 : id32;   // int64 view has zero odd words

    const int b = row / T;
    const int t = row - b * T;

    // pt loads (id-independent, L2-hot): in flight during id selection.
    const float4* pt4 = (const float4*)(g_pt + t * HD);
    float4 pt[3];
    #pragma unroll
    for (int j = 0; j < 3; j++) pt[j] = pt4[h0 + 64 * j];

    const float* src;
    const bool use_ocr = (id >= V);
    if (use_ocr) {
        int oi = id - V;
        if (oi > N - 1) oi = N - 1;
        src = ocr + ((long long)b * N + oi) * HD;
    } else {
        int ci = id < 0 ? 0 : (id > V - 1 ? V - 1 : id);
        src = cv + (long long)ci * HD;
    }
    const float4* s4 = (const float4*)src;

    float4 x[3];
    #pragma unroll
    for (int j = 0; j < 3; j++) x[j] = s4[h0 + 64 * j];

    float sx = 0.f, sxx = 0.f;
    #pragma unroll
    for (int j = 0; j < 3; j++) {
        sx  += x[j].x + x[j].y + x[j].z + x[j].w;
        sxx += x[j].x*x[j].x + x[j].y*x[j].y + x[j].z*x[j].z + x[j].w*x[j].w;
    }
    #pragma unroll
    for (int off = 16; off > 0; off >>= 1) {
        sx  += __shfl_xor_sync(0xFFFFFFFFu, sx,  off);
        sxx += __shfl_xor_sync(0xFFFFFFFFu, sxx, off);
    }

    // cross-warp combine within the pair: independent named barrier per pair
    if (lane == 0) s_red[pair][wip] = make_float2(sx, sxx);
    asm volatile("bar.sync %0, 64;" :: "r"(pair) : "memory");
    const float2 r0 = s_red[pair][0];
    const float2 r1 = s_red[pair][1];

    const float inv_h = 1.0f / (float)HD;
    const float mu_x = (r0.x + r1.x) * inv_h;
    const float rx   = rsqrtf(fmaxf((r0.y + r1.y) * inv_h - mu_x * mu_x, 0.f) + LN_EPS);

    const float4* gm = (const float4*)(use_ocr ? ocr_g : cv_g);
    const float4* bm = (const float4*)(use_ocr ? ocr_b : cv_b);
    float4* o = (float4*)(out + (long long)row * HD);

    #pragma unroll
    for (int j = 0; j < 3; j++) {
        const int h = h0 + 64 * j;
        const float4 g  = gm[h];
        const float4 bb = bm[h];
        float4 r;
        r.x = (x[j].x - mu_x) * rx * g.x + bb.x + pt[j].x;
        r.y = (x[j].y - mu_x) * rx * g.y + bb.y + pt[j].y;
        r.z = (x[j].z - mu_x) * rx * g.z + bb.z + pt[j].z;
        r.w = (x[j].w - mu_x) * rx * g.w + bb.w + pt[j].w;
        stcs4(o + h, r);
    }
}

extern "C" void kernel_launch(void* const* d_in, const int* in_sizes, int n_in,
                              void* d_out, int out_size) {
    const float* cv       = (const float*)d_in[0];   // [V, H]
    const float* ocr      = (const float*)d_in[1];   // [B, N, H]
    const int*   ids_raw  = (const int*)d_in[2];     // [B, T] int32 or int64
    const float* cv_g     = (const float*)d_in[3];
    const float* cv_b     = (const float*)d_in[4];
    const float* ocr_g    = (const float*)d_in[5];
    const float* ocr_b    = (const float*)d_in[6];
    const float* pos_emb  = (const float*)d_in[7];   // [T, H]
    const float* type_emb = (const float*)d_in[8];   // [2, H]
    const float* emb_g    = (const float*)d_in[9];
    const float* emb_b    = (const float*)d_in[10];
    float* out = (float*)d_out;

    const int Hs = in_sizes[3];             // 768
    const int V  = in_sizes[0] / Hs;        // 32000
    const int T  = in_sizes[7] / Hs;        // 128
    const int BT = in_sizes[2];             // 2048
    const int B  = BT / T;                  // 16
    const int N  = in_sizes[1] / (B * Hs);  // 50

    pt_kernel<<<(T + 3) / 4, 128>>>(pos_emb, type_emb, emb_g, emb_b, V, T);

    const int grid = (BT + RPC - 1) / RPC;  // 512
    prev_embedding_kernel<<<grid, TPB>>>(cv, ocr, ids_raw,
                                         cv_g, cv_b, ocr_g, ocr_b,
                                         out, V, N, T, BT);
}